// round 11
// baseline (speedup 1.0000x reference)
#include <cuda_runtime.h>
#include <cstdint>

// PCEN: EMA over time + pointwise compression.
// x: [B=32, T=8192, F=128] f32.  out same shape.
//
// Chunked EMA, 256-step warm-up (seed decay 0.975^256 ~ 1.5e-3 -> measured
// rel_err ~2e-4, safely under the 1e-3 gate; do NOT shrink warm further).
// F split across 4 warps per (b, chunk): 32 lanes x f32 = one 128B line per
// time step (perfectly coalesced). 4096 warps total -> ~28 warps/SM, same
// byte traffic as before, 2x the latency hiding. Depth-16 scalar ring.

#define T_DIM   8192
#define F_DIM   128
#define B_DIM   32
#define L_CHUNK 256
#define N_CHUNK (T_DIM / L_CHUNK)   // 32
#define WARM    256
#define RDEPTH  16                  // ring depth (f32 rows in flight)
#define WARPS_PER_BLOCK 8           // 256 threads/block

#define EPS_C    1e-6f
#define S_C      0.025f
#define OMS_C    0.975f
#define ALPHA_C  0.98f
#define SQRT_DELTA_C 1.41421356237309515f  // sqrt(2.0)

__device__ __forceinline__ float sqrt_approx(float x) {
    float y;
    asm("sqrt.approx.f32 %0, %1;" : "=f"(y) : "f"(x));
    return y;
}
__device__ __forceinline__ float lg2_approx(float x) {
    float y;
    asm("lg2.approx.f32 %0, %1;" : "=f"(y) : "f"(x));
    return y;
}
__device__ __forceinline__ float ex2_approx(float x) {
    float y;
    asm("ex2.approx.f32 %0, %1;" : "=f"(y) : "f"(x));
    return y;
}

// (m + eps)^(-alpha) via MUFU lg2/ex2
__device__ __forceinline__ float inv_pow_alpha(float m) {
    return ex2_approx(-ALPHA_C * lg2_approx(m + EPS_C));
}

__device__ __forceinline__ float pcen_out(float xv, float m) {
    return sqrt_approx(fmaf(xv, inv_pow_alpha(m), 2.0f)) - SQRT_DELTA_C;
}

__device__ __forceinline__ void store_cs(float* p, float v) {
    asm volatile("st.global.cs.f32 [%0], %1;" :: "l"(p), "f"(v) : "memory");
}

__global__ void __launch_bounds__(32 * WARPS_PER_BLOCK, 4)
pcen_kernel(const float* __restrict__ x, float* __restrict__ out) {
    const int lane = threadIdx.x & 31;
    const int wid  = blockIdx.x * WARPS_PER_BLOCK + (threadIdx.x >> 5);

    const int q  = wid & 3;                       // F quarter (0..3)
    const int cw = wid >> 2;                      // chunk-warp id
    const int b  = cw / N_CHUNK;
    const int c  = cw % N_CHUNK;

    const int warm = (c == 0) ? 0 : WARM;
    const int t_s  = c * L_CHUNK - warm;          // first time step this warp touches
    const int N    = L_CHUNK + warm;              // total steps (multiple of RDEPTH)

    const size_t base = (size_t)(b * T_DIM + t_s) * F_DIM + q * 32 + lane;
    const float* px = x   + base;
    float*       po = out + base;

    // ---- prologue: fill ring ----
    float buf[RDEPTH];
#pragma unroll
    for (int i = 0; i < RDEPTH; i++)
        buf[i] = px[(size_t)i * F_DIM];

    // Seed m = x[t_s]; the EMA update with m == x is a fixed point, so the
    // first iteration needs no special case. Chunk 0: exact M[0] = x[0].
    float m = buf[0];

    int r = 0;

    // ---- warm-up tiles: EMA only, no output ----
    for (; r < warm; r += RDEPTH) {
#pragma unroll
        for (int i = 0; i < RDEPTH; i++) {
            float xv = buf[i];
            int nidx = min(r + RDEPTH + i, N - 1);   // clamp (redundant re-read, safe)
            buf[i] = px[(size_t)nidx * F_DIM];       // refill slot: depth-16 pipeline
            m = fmaf(OMS_C, m, S_C * xv);
        }
    }

    // ---- emit tiles: EMA + PCEN output ----
    for (; r < N; r += RDEPTH) {
#pragma unroll
        for (int i = 0; i < RDEPTH; i++) {
            float xv = buf[i];
            int nidx = min(r + RDEPTH + i, N - 1);
            buf[i] = px[(size_t)nidx * F_DIM];
            m = fmaf(OMS_C, m, S_C * xv);
            store_cs(po + (size_t)(r + i) * F_DIM, pcen_out(xv, m));
        }
    }
}

extern "C" void kernel_launch(void* const* d_in, const int* in_sizes, int n_in,
                              void* d_out, int out_size) {
    (void)in_sizes; (void)n_in; (void)out_size;
    const float* x = (const float*)d_in[0];
    float* o = (float*)d_out;
    const int total_warps = B_DIM * N_CHUNK * 4;             // 4096
    pcen_kernel<<<total_warps / WARPS_PER_BLOCK, 32 * WARPS_PER_BLOCK>>>(x, o);
}

// round 13
// speedup vs baseline: 1.0887x; 1.0887x over previous
#include <cuda_runtime.h>
#include <cstdint>

// PCEN: EMA over time + pointwise compression.
// x: [B=32, T=8192, F=128] f32.  out same shape.
//
// Chunked EMA, 256-step warm-up (seed decay 0.975^256 ~ 1.5e-3 -> measured
// rel_err ~2e-4, safely under the 1e-3 gate; do NOT shrink warm further).
// F split across 2 warps per (b, chunk): 32 lanes x float2 = 256B row/step.
// 2048 warps. Depth-32 float2 ring -> 8KB/warp in flight (R9 had 16/4KB;
// scalar 4-way split regressed: instruction overhead > occupancy gain).

#define T_DIM   8192
#define F_DIM   128
#define B_DIM   32
#define L_CHUNK 256
#define N_CHUNK (T_DIM / L_CHUNK)   // 32
#define WARM    256
#define RDEPTH  32                  // ring depth (float2 rows in flight)
#define WARPS_PER_BLOCK 8           // 256 threads/block

#define EPS_C    1e-6f
#define S_C      0.025f
#define OMS_C    0.975f
#define ALPHA_C  0.98f
#define SQRT_DELTA_C 1.41421356237309515f  // sqrt(2.0)

__device__ __forceinline__ float sqrt_approx(float x) {
    float y;
    asm("sqrt.approx.f32 %0, %1;" : "=f"(y) : "f"(x));
    return y;
}
__device__ __forceinline__ float lg2_approx(float x) {
    float y;
    asm("lg2.approx.f32 %0, %1;" : "=f"(y) : "f"(x));
    return y;
}
__device__ __forceinline__ float ex2_approx(float x) {
    float y;
    asm("ex2.approx.f32 %0, %1;" : "=f"(y) : "f"(x));
    return y;
}

// (m + eps)^(-alpha) via MUFU lg2/ex2
__device__ __forceinline__ float inv_pow_alpha(float m) {
    return ex2_approx(-ALPHA_C * lg2_approx(m + EPS_C));
}

__device__ __forceinline__ void ema_update(float2& m, const float2& xv) {
    m.x = fmaf(OMS_C, m.x, S_C * xv.x);
    m.y = fmaf(OMS_C, m.y, S_C * xv.y);
}

__device__ __forceinline__ float2 pcen_out(const float2& xv, const float2& m) {
    float2 o;
    o.x = sqrt_approx(fmaf(xv.x, inv_pow_alpha(m.x), 2.0f)) - SQRT_DELTA_C;
    o.y = sqrt_approx(fmaf(xv.y, inv_pow_alpha(m.y), 2.0f)) - SQRT_DELTA_C;
    return o;
}

__device__ __forceinline__ void store_cs(float2* p, const float2& v) {
    asm volatile("st.global.cs.v2.f32 [%0], {%1,%2};"
                 :: "l"(p), "f"(v.x), "f"(v.y) : "memory");
}

__global__ void __launch_bounds__(32 * WARPS_PER_BLOCK, 2)
pcen_kernel(const float2* __restrict__ x, float2* __restrict__ out) {
    const int lane = threadIdx.x & 31;
    const int wid  = blockIdx.x * WARPS_PER_BLOCK + (threadIdx.x >> 5);

    const int half = wid & 1;                     // which F half (0: f<64, 1: f>=64)
    const int cw   = wid >> 1;                    // chunk-warp id
    const int b    = cw / N_CHUNK;
    const int c    = cw % N_CHUNK;

    const int warm = (c == 0) ? 0 : WARM;
    const int t_s  = c * L_CHUNK - warm;          // first time step this warp touches
    const int N    = L_CHUNK + warm;              // total steps (multiple of RDEPTH)

    const int ROWF2 = F_DIM / 2;                  // 64 float2 per time row

    const size_t base = (size_t)(b * T_DIM + t_s) * ROWF2 + half * 32 + lane;
    const float2* px = x   + base;
    float2*       po = out + base;

    // ---- prologue: fill ring ----
    float2 buf[RDEPTH];
#pragma unroll
    for (int i = 0; i < RDEPTH; i++)
        buf[i] = px[(size_t)i * ROWF2];

    // Seed m = x[t_s]; ema_update(m, x) with m == x is a fixed point, so the
    // first iteration needs no special case. Chunk 0: exact M[0] = x[0].
    float2 m = buf[0];

    int r = 0;

    // ---- warm-up tiles: EMA only, no output ----
    for (; r < warm; r += RDEPTH) {
#pragma unroll
        for (int i = 0; i < RDEPTH; i++) {
            float2 xv = buf[i];
            int nidx = min(r + RDEPTH + i, N - 1);   // clamp (redundant re-read, safe)
            buf[i] = px[(size_t)nidx * ROWF2];       // refill slot: depth-32 pipeline
            ema_update(m, xv);
        }
    }

    // ---- emit tiles: EMA + PCEN output ----
    for (; r < N; r += RDEPTH) {
#pragma unroll
        for (int i = 0; i < RDEPTH; i++) {
            float2 xv = buf[i];
            int nidx = min(r + RDEPTH + i, N - 1);
            buf[i] = px[(size_t)nidx * ROWF2];
            ema_update(m, xv);
            store_cs(po + (size_t)(r + i) * ROWF2, pcen_out(xv, m));
        }
    }
}

extern "C" void kernel_launch(void* const* d_in, const int* in_sizes, int n_in,
                              void* d_out, int out_size) {
    (void)in_sizes; (void)n_in; (void)out_size;
    const float2* x = (const float2*)d_in[0];
    float2* o = (float2*)d_out;
    const int total_warps = B_DIM * N_CHUNK * 2;             // 2048
    pcen_kernel<<<total_warps / WARPS_PER_BLOCK, 32 * WARPS_PER_BLOCK>>>(x, o);
}